// round 3
// baseline (speedup 1.0000x reference)
#include <cuda_runtime.h>
#include <cuda_bf16.h>

// DCTPolicy: out = [coeffs (3*4096*4096 f32), log_prob, entropy]
// Gather formulation: each output float4 lane computes its (c,h,w), derives
// (u,v) within the 8x8 block, and if (u,v) is one of the 16 kept zig-zag
// coefficients, gathers the param at ((c*512+bh)*512+bw)*16 + zigzag_rank.
// Reductions (sum eps^2, sum log_std) fused into the same pass since each
// param is touched exactly once.

#define CC   3
#define HH   4096
#define WW   4096
#define CHW  (CC * HH * WW)          // 50331648
#define NPAR 12582912                 // C * 512 * 512 * 16

__device__ double g_acc[2];           // [0] = sum(eps^2), [1] = sum(log_std)

// zigzag rank within 8x8 block for the first 16 coefficients; -1 = not kept.
// Row u, columns v=0..7.
__constant__ signed char RANK[64] = {
     0,  2,  3,  9, 10, -1, -1, -1,   // u=0
     1,  4,  8, 11, -1, -1, -1, -1,   // u=1
     5,  7, 12, -1, -1, -1, -1, -1,   // u=2
     6, 13, -1, -1, -1, -1, -1, -1,   // u=3
    14, -1, -1, -1, -1, -1, -1, -1,   // u=4
    15, -1, -1, -1, -1, -1, -1, -1,   // u=5
    -1, -1, -1, -1, -1, -1, -1, -1,   // u=6
    -1, -1, -1, -1, -1, -1, -1, -1    // u=7
};

__global__ void zero_acc_kernel() {
    g_acc[0] = 0.0;
    g_acc[1] = 0.0;
}

__global__ __launch_bounds__(256, 8)
void dct_gather_kernel(const float* __restrict__ mean,
                       const float* __restrict__ lstd,
                       const float* __restrict__ eps,
                       float* __restrict__ out)
{
    // q = float4 index into coeffs. Total = CHW/4 = 12,582,912 = 49152*256.
    int q  = blockIdx.x * 256 + threadIdx.x;
    int w4 = q & 1023;          // W/4 = 1024 float4 per row
    int hc = q >> 10;
    int h  = hc & 4095;
    int c  = hc >> 12;
    int u  = h & 7;             // uniform within a block (block = 1/4 row)

    float4 val = make_float4(0.f, 0.f, 0.f, 0.f);
    float s1 = 0.f, s2 = 0.f;

    if (u < 6) {
        int w0 = w4 << 2;       // first column this float4 covers
        int v0 = w0 & 7;        // 0 or 4
        int bw = w0 >> 3;
        int bh = h >> 3;
        int base = (((c << 9) + bh) << 9 | bw) << 4;  // ((c*512+bh)*512+bw)*16
        float vals[4] = {0.f, 0.f, 0.f, 0.f};
        #pragma unroll
        for (int j = 0; j < 4; j++) {
            int r = RANK[(u << 3) + v0 + j];
            if (r >= 0) {
                int p   = base + r;
                float m = __ldg(mean + p);
                float l = __ldg(lstd + p);
                float e = __ldg(eps  + p);
                vals[j] = fmaf(__expf(l), e, m);   // COEFF_SCALE = 1
                s1 = fmaf(e, e, s1);
                s2 += l;
            }
        }
        val.x = vals[0]; val.y = vals[1]; val.z = vals[2]; val.w = vals[3];
    }

    reinterpret_cast<float4*>(out)[q] = val;

    // Reduction: only blocks with u<6 carry nonzero contributions (uniform
    // per block, so this branch is convergent around __syncthreads).
    if (u < 6) {
        #pragma unroll
        for (int off = 16; off > 0; off >>= 1) {
            s1 += __shfl_down_sync(0xffffffffu, s1, off);
            s2 += __shfl_down_sync(0xffffffffu, s2, off);
        }
        __shared__ float sh1[8], sh2[8];
        int lane = threadIdx.x & 31;
        int wrp  = threadIdx.x >> 5;
        if (lane == 0) { sh1[wrp] = s1; sh2[wrp] = s2; }
        __syncthreads();
        if (threadIdx.x == 0) {
            float t1 = 0.f, t2 = 0.f;
            #pragma unroll
            for (int i = 0; i < 8; i++) { t1 += sh1[i]; t2 += sh2[i]; }
            atomicAdd(&g_acc[0], (double)t1);
            atomicAdd(&g_acc[1], (double)t2);
        }
    }
}

__global__ void finalize_kernel(float* __restrict__ out, int out_size)
{
    const double LOG2PI = 1.8378770664093454836;
    double S1 = g_acc[0];
    double S2 = g_acc[1];
    double lp  = -0.5 * (S1 + 2.0 * S2 + (double)NPAR * LOG2PI);
    double ent = (double)NPAR * 0.5 * (1.0 + LOG2PI) + S2;
    if (out_size >= CHW + 2) {
        out[CHW]     = (float)lp;
        out[CHW + 1] = (float)ent;
    }
}

extern "C" void kernel_launch(void* const* d_in, const int* in_sizes, int n_in,
                              void* d_out, int out_size)
{
    const float* mean = (const float*)d_in[0];
    const float* lstd = (const float*)d_in[1];
    const float* eps  = (const float*)d_in[2];
    // d_in[3] = flat_idx — unused; the index map is computed analytically.
    float* out = (float*)d_out;

    zero_acc_kernel<<<1, 1>>>();
    dct_gather_kernel<<<CHW / 4 / 256, 256>>>(mean, lstd, eps, out);
    finalize_kernel<<<1, 1>>>(out, out_size);
}

// round 4
// speedup vs baseline: 2.3618x; 2.3618x over previous
#include <cuda_runtime.h>
#include <cuda_bf16.h>

// DCTPolicy: out = [coeffs (3*4096*4096 f32), log_prob, entropy]
//
// Tile formulation: each CTA owns an 8-row x 2048-col output tile, which maps
// to 256 consecutive 8x8 blocks = 4096 CONTIGUOUS params per array.
//   Phase 1: coalesced float4 loads of mean/log_std/eps, compute sample,
//            stage into smem (transposed layout, padded stride), accumulate
//            the two reductions in registers.
//   Phase 2: coalesced float4 stores of the full tile, gathering kept
//            coefficients from smem via the constant zig-zag rank table.
// Reductions go to per-CTA partial slots (no zero-init kernel needed);
// a tiny finalize kernel reduces 3072 partials and writes the 2 scalars.

#define CC    3
#define HH    4096
#define WW    4096
#define CHW   (CC * HH * WW)            // 50331648
#define NPAR  12582912                   // C * 512 * 512 * 16
#define NTILE 3072                       // C * 512 * 2 tiles (8 x 2048 each)
#define SMSTRIDE 258                     // 16 ranks * 258 floats (padded)

__device__ float g_p1[NTILE];            // per-CTA sum(eps^2)
__device__ float g_p2[NTILE];            // per-CTA sum(log_std)

// zigzag rank within 8x8 block for the first 16 coefficients; -1 = not kept.
__constant__ signed char RANK[64] = {
     0,  2,  3,  9, 10, -1, -1, -1,   // u=0
     1,  4,  8, 11, -1, -1, -1, -1,   // u=1
     5,  7, 12, -1, -1, -1, -1, -1,   // u=2
     6, 13, -1, -1, -1, -1, -1, -1,   // u=3
    14, -1, -1, -1, -1, -1, -1, -1,   // u=4
    15, -1, -1, -1, -1, -1, -1, -1,   // u=5
    -1, -1, -1, -1, -1, -1, -1, -1,   // u=6
    -1, -1, -1, -1, -1, -1, -1, -1    // u=7
};

__global__ __launch_bounds__(256)
void dct_tile_kernel(const float* __restrict__ mean,
                     const float* __restrict__ lstd,
                     const float* __restrict__ eps,
                     float* __restrict__ out)
{
    __shared__ float sm[16 * SMSTRIDE];   // sm[rank*258 + blk], 16.5 KB

    const int tile = blockIdx.x;          // 0..3071
    const int c    = tile >> 10;          // tile / 1024
    const int rr   = tile & 1023;
    const int bh   = rr >> 1;             // block-row 0..511
    const int tw   = rr & 1;              // which 2048-col half
    const int tid  = threadIdx.x;

    // param base for this tile: ((c*512 + bh)*512 + tw*256) * 16 floats
    const int base = ((((c << 9) + bh) << 9) + (tw << 8)) << 4;
    const float4* m4 = (const float4*)(mean + base);
    const float4* l4 = (const float4*)(lstd + base);
    const float4* e4 = (const float4*)(eps  + base);

    float s1 = 0.f, s2 = 0.f;

    // ---- Phase 1: coalesced param load + sample + stage to smem ----
    #pragma unroll
    for (int k = 0; k < 4; k++) {
        int f = tid + (k << 8);           // float4 index, 0..1023
        float4 m = m4[f];
        float4 l = l4[f];
        float4 e = e4[f];
        float4 s;
        s.x = fmaf(__expf(l.x), e.x, m.x);
        s.y = fmaf(__expf(l.y), e.y, m.y);
        s.z = fmaf(__expf(l.z), e.z, m.z);
        s.w = fmaf(__expf(l.w), e.w, m.w);
        s1 = fmaf(e.x, e.x, s1); s1 = fmaf(e.y, e.y, s1);
        s1 = fmaf(e.z, e.z, s1); s1 = fmaf(e.w, e.w, s1);
        s2 += (l.x + l.y) + (l.z + l.w);
        int p = f << 2;                   // param index within tile
        // transposed, padded: conflict-free stores (verified bank math)
        sm[((p + 0) & 15) * SMSTRIDE + ((p + 0) >> 4)] = s.x;
        sm[((p + 1) & 15) * SMSTRIDE + ((p + 1) >> 4)] = s.y;
        sm[((p + 2) & 15) * SMSTRIDE + ((p + 2) >> 4)] = s.z;
        sm[((p + 3) & 15) * SMSTRIDE + ((p + 3) >> 4)] = s.w;
    }
    __syncthreads();

    // ---- Phase 2: coalesced tile store with smem gather ----
    const int hbase   = bh << 3;
    const int rowbase = ((c << 12) + hbase);   // global row of u=0
    float4* out4 = (float4*)out;

    #pragma unroll
    for (int k = 0; k < 16; k++) {
        int f    = tid + (k << 8);        // 0..4095 (tile float4 index)
        int u    = f >> 9;                // row within tile, 0..7
        int col4 = f & 511;               // float4 col within tile
        int half = col4 & 1;              // v0 = 4*half
        int blk  = col4 >> 1;             // block within tile, 0..255
        int ri   = (u << 3) + (half << 2);
        float4 v;
        int r0 = RANK[ri + 0];
        int r1 = RANK[ri + 1];
        int r2 = RANK[ri + 2];
        int r3 = RANK[ri + 3];
        v.x = (r0 >= 0) ? sm[r0 * SMSTRIDE + blk] : 0.f;
        v.y = (r1 >= 0) ? sm[r1 * SMSTRIDE + blk] : 0.f;
        v.z = (r2 >= 0) ? sm[r2 * SMSTRIDE + blk] : 0.f;
        v.w = (r3 >= 0) ? sm[r3 * SMSTRIDE + blk] : 0.f;
        int o = (rowbase + u) * 1024 + (tw << 9) + col4;
        out4[o] = v;
    }

    // ---- Reduction: warp shfl -> shared -> per-CTA partial slot ----
    #pragma unroll
    for (int off = 16; off > 0; off >>= 1) {
        s1 += __shfl_down_sync(0xffffffffu, s1, off);
        s2 += __shfl_down_sync(0xffffffffu, s2, off);
    }
    __shared__ float sh1[8], sh2[8];
    int lane = tid & 31, wrp = tid >> 5;
    if (lane == 0) { sh1[wrp] = s1; sh2[wrp] = s2; }
    __syncthreads();
    if (tid == 0) {
        float t1 = 0.f, t2 = 0.f;
        #pragma unroll
        for (int i = 0; i < 8; i++) { t1 += sh1[i]; t2 += sh2[i]; }
        g_p1[tile] = t1;
        g_p2[tile] = t2;
    }
}

__global__ __launch_bounds__(1024)
void finalize_kernel(float* __restrict__ out, int out_size)
{
    int tid = threadIdx.x;
    double t1 = 0.0, t2 = 0.0;
    for (int i = tid; i < NTILE; i += 1024) {
        t1 += (double)g_p1[i];
        t2 += (double)g_p2[i];
    }
    #pragma unroll
    for (int off = 16; off > 0; off >>= 1) {
        t1 += __shfl_down_sync(0xffffffffu, t1, off);
        t2 += __shfl_down_sync(0xffffffffu, t2, off);
    }
    __shared__ double sh1[32], sh2[32];
    int lane = tid & 31, wrp = tid >> 5;
    if (lane == 0) { sh1[wrp] = t1; sh2[wrp] = t2; }
    __syncthreads();
    if (tid == 0) {
        double S1 = 0.0, S2 = 0.0;
        #pragma unroll
        for (int i = 0; i < 32; i++) { S1 += sh1[i]; S2 += sh2[i]; }
        const double LOG2PI = 1.8378770664093454836;
        double lp  = -0.5 * (S1 + 2.0 * S2 + (double)NPAR * LOG2PI);
        double ent = (double)NPAR * 0.5 * (1.0 + LOG2PI) + S2;
        if (out_size >= CHW + 2) {
            out[CHW]     = (float)lp;
            out[CHW + 1] = (float)ent;
        }
    }
}

extern "C" void kernel_launch(void* const* d_in, const int* in_sizes, int n_in,
                              void* d_out, int out_size)
{
    const float* mean = (const float*)d_in[0];
    const float* lstd = (const float*)d_in[1];
    const float* eps  = (const float*)d_in[2];
    // d_in[3] = flat_idx — unused; index map computed analytically.
    float* out = (float*)d_out;

    dct_tile_kernel<<<NTILE, 256>>>(mean, lstd, eps, out);
    finalize_kernel<<<1, 1024>>>(out, out_size);
}

// round 5
// speedup vs baseline: 2.4910x; 1.0547x over previous
#include <cuda_runtime.h>
#include <cuda_bf16.h>

// DCTPolicy: out = [coeffs (3*4096*4096 f32), log_prob, entropy]
//
// Single fused kernel. Each CTA owns an 8-row x 2048-col output tile
// (= 256 consecutive 8x8 blocks = 4096 CONTIGUOUS params per array):
//   Phase 1: coalesced float4 loads of mean/log_std/eps, compute sample,
//            stage into smem (transposed, padded stride), accumulate the
//            two reductions in registers.
//   Phase 2: coalesced float4 stores of the full tile, gathering kept
//            coefficients from smem via the constant zig-zag rank table.
//   Tail:    per-CTA partials -> global slots; the LAST CTA to finish
//            (atomic counter) reduces all 3072 partials in double and
//            writes the two scalars, then resets the counter (so the
//            kernel is graph-replay deterministic).

#define CC    3
#define HH    4096
#define WW    4096
#define CHW   (CC * HH * WW)            // 50331648
#define NPAR  12582912                   // C * 512 * 512 * 16
#define NTILE 3072                       // C * 512 * 2 tiles (8 x 2048 each)
#define SMSTRIDE 258                     // 16 ranks * 258 floats (padded)

__device__ float g_p1[NTILE];            // per-CTA sum(eps^2)
__device__ float g_p2[NTILE];            // per-CTA sum(log_std)
__device__ int   g_done = 0;             // completion counter (reset by last CTA)

// zigzag rank within 8x8 block for the first 16 coefficients; -1 = not kept.
__constant__ signed char RANK[64] = {
     0,  2,  3,  9, 10, -1, -1, -1,   // u=0
     1,  4,  8, 11, -1, -1, -1, -1,   // u=1
     5,  7, 12, -1, -1, -1, -1, -1,   // u=2
     6, 13, -1, -1, -1, -1, -1, -1,   // u=3
    14, -1, -1, -1, -1, -1, -1, -1,   // u=4
    15, -1, -1, -1, -1, -1, -1, -1,   // u=5
    -1, -1, -1, -1, -1, -1, -1, -1,   // u=6
    -1, -1, -1, -1, -1, -1, -1, -1    // u=7
};

__global__ __launch_bounds__(256)
void dct_tile_kernel(const float* __restrict__ mean,
                     const float* __restrict__ lstd,
                     const float* __restrict__ eps,
                     float* __restrict__ out, int out_size)
{
    __shared__ float sm[16 * SMSTRIDE];   // sm[rank*258 + blk], 16.5 KB

    const int tile = blockIdx.x;          // 0..3071
    const int c    = tile >> 10;          // tile / 1024
    const int rr   = tile & 1023;
    const int bh   = rr >> 1;             // block-row 0..511
    const int tw   = rr & 1;              // which 2048-col half
    const int tid  = threadIdx.x;

    // param base for this tile: ((c*512 + bh)*512 + tw*256) * 16 floats
    const int base = ((((c << 9) + bh) << 9) + (tw << 8)) << 4;
    const float4* m4 = (const float4*)(mean + base);
    const float4* l4 = (const float4*)(lstd + base);
    const float4* e4 = (const float4*)(eps  + base);

    float s1 = 0.f, s2 = 0.f;

    // ---- Phase 1: coalesced param load + sample + stage to smem ----
    #pragma unroll
    for (int k = 0; k < 4; k++) {
        int f = tid + (k << 8);           // float4 index, 0..1023
        float4 m = m4[f];
        float4 l = l4[f];
        float4 e = e4[f];
        float4 s;
        s.x = fmaf(__expf(l.x), e.x, m.x);
        s.y = fmaf(__expf(l.y), e.y, m.y);
        s.z = fmaf(__expf(l.z), e.z, m.z);
        s.w = fmaf(__expf(l.w), e.w, m.w);
        s1 = fmaf(e.x, e.x, s1); s1 = fmaf(e.y, e.y, s1);
        s1 = fmaf(e.z, e.z, s1); s1 = fmaf(e.w, e.w, s1);
        s2 += (l.x + l.y) + (l.z + l.w);
        int p = f << 2;                   // param index within tile
        sm[((p + 0) & 15) * SMSTRIDE + ((p + 0) >> 4)] = s.x;
        sm[((p + 1) & 15) * SMSTRIDE + ((p + 1) >> 4)] = s.y;
        sm[((p + 2) & 15) * SMSTRIDE + ((p + 2) >> 4)] = s.z;
        sm[((p + 3) & 15) * SMSTRIDE + ((p + 3) >> 4)] = s.w;
    }
    __syncthreads();

    // ---- Phase 2: coalesced tile store with smem gather ----
    const int rowbase = (c << 12) + (bh << 3);   // global row of u=0
    float4* out4 = (float4*)out;

    #pragma unroll
    for (int k = 0; k < 16; k++) {
        int f    = tid + (k << 8);        // 0..4095 (tile float4 index)
        int u    = f >> 9;                // row within tile, 0..7
        int col4 = f & 511;               // float4 col within tile
        int half = col4 & 1;              // v0 = 4*half
        int blk  = col4 >> 1;             // block within tile, 0..255
        int ri   = (u << 3) + (half << 2);
        float4 v;
        int r0 = RANK[ri + 0];
        int r1 = RANK[ri + 1];
        int r2 = RANK[ri + 2];
        int r3 = RANK[ri + 3];
        v.x = (r0 >= 0) ? sm[r0 * SMSTRIDE + blk] : 0.f;
        v.y = (r1 >= 0) ? sm[r1 * SMSTRIDE + blk] : 0.f;
        v.z = (r2 >= 0) ? sm[r2 * SMSTRIDE + blk] : 0.f;
        v.w = (r3 >= 0) ? sm[r3 * SMSTRIDE + blk] : 0.f;
        int o = (rowbase + u) * 1024 + (tw << 9) + col4;
        out4[o] = v;
    }

    // ---- Per-CTA reduction: warp shfl -> shared -> partial slot ----
    #pragma unroll
    for (int off = 16; off > 0; off >>= 1) {
        s1 += __shfl_down_sync(0xffffffffu, s1, off);
        s2 += __shfl_down_sync(0xffffffffu, s2, off);
    }
    __shared__ float sh1[8], sh2[8];
    __shared__ int is_last;
    int lane = tid & 31, wrp = tid >> 5;
    if (lane == 0) { sh1[wrp] = s1; sh2[wrp] = s2; }
    __syncthreads();
    if (tid == 0) {
        float t1 = 0.f, t2 = 0.f;
        #pragma unroll
        for (int i = 0; i < 8; i++) { t1 += sh1[i]; t2 += sh2[i]; }
        g_p1[tile] = t1;
        g_p2[tile] = t2;
        __threadfence();                     // make partials visible
        int old = atomicAdd(&g_done, 1);
        is_last = (old == NTILE - 1);
    }
    __syncthreads();

    // ---- Last CTA: final reduction over all 3072 partials ----
    if (is_last) {
        double t1 = 0.0, t2 = 0.0;
        for (int i = tid; i < NTILE; i += 256) {
            t1 += (double)g_p1[i];
            t2 += (double)g_p2[i];
        }
        #pragma unroll
        for (int off = 16; off > 0; off >>= 1) {
            t1 += __shfl_down_sync(0xffffffffu, t1, off);
            t2 += __shfl_down_sync(0xffffffffu, t2, off);
        }
        __shared__ double dh1[8], dh2[8];
        if (lane == 0) { dh1[wrp] = t1; dh2[wrp] = t2; }
        __syncthreads();
        if (tid == 0) {
            double S1 = 0.0, S2 = 0.0;
            #pragma unroll
            for (int i = 0; i < 8; i++) { S1 += dh1[i]; S2 += dh2[i]; }
            const double LOG2PI = 1.8378770664093454836;
            double lp  = -0.5 * (S1 + 2.0 * S2 + (double)NPAR * LOG2PI);
            double ent = (double)NPAR * 0.5 * (1.0 + LOG2PI) + S2;
            if (out_size >= CHW + 2) {
                out[CHW]     = (float)lp;
                out[CHW + 1] = (float)ent;
            }
            g_done = 0;                      // reset for next graph replay
        }
    }
}

extern "C" void kernel_launch(void* const* d_in, const int* in_sizes, int n_in,
                              void* d_out, int out_size)
{
    const float* mean = (const float*)d_in[0];
    const float* lstd = (const float*)d_in[1];
    const float* eps  = (const float*)d_in[2];
    // d_in[3] = flat_idx — unused; index map computed analytically.
    float* out = (float*)d_out;

    dct_tile_kernel<<<NTILE, 256>>>(mean, lstd, eps, out, out_size);
}